// round 6
// baseline (speedup 1.0000x reference)
#include <cuda_runtime.h>
#include <cuda_bf16.h>
#include <cstdint>

#define MAXN   500000
#define IN     128
#define H1     32
#define H2     32
#define NOS    4
#define TM     128
#define MAXNB  3912
#define PADN   (MAXNB * TM)
#define MAXCB  1954                  // ceil(MAXN/256)

typedef unsigned long long ull;

// ---- smem byte offsets (k_mlp) ----
#define OFF_S     0          // A staging fp32 [128][132] = 67584
#define OFF_W0    67584      // W0 tf32 [k=128][40]       = 20480
#define OFF_H     88064      // h bf16  [128][40]         = 10240
#define OFF_W1    98304      // W1 bf16 [c=32][40]        = 2560
#define OFF_B0    100864
#define OFF_B1    100992
#define OFF_W2    101120
#define OFF_B2    101248
#define OFF_SIDX  101264     // 128 ints
#define OFF_SRED  101776     // 128 floats
#define SMEM_BYTES 102400

__device__ __forceinline__ float fast_tanh(float x) {
    float e, r;
    asm("ex2.approx.f32 %0, %1;" : "=f"(e) : "f"(x * 2.885390081777927f));
    asm("rcp.approx.f32 %0, %1;" : "=f"(r) : "f"(e + 1.0f));
    return fmaf(-2.0f, r, 1.0f);
}
__device__ __forceinline__ uint32_t f2tf32(float x) {
    uint32_t r;
    asm("cvt.rna.tf32.f32 %0, %1;" : "=r"(r) : "f"(x));
    return r;
}
__device__ __forceinline__ uint32_t packbf2(float lo, float hi) {
    __nv_bfloat162 p = __floats2bfloat162_rn(lo, hi);
    return *(uint32_t*)&p;
}
__device__ __forceinline__ void mma8(float& d0, float& d1, float& d2, float& d3,
                                     uint32_t a0, uint32_t a1, uint32_t a2, uint32_t a3,
                                     uint32_t b0, uint32_t b1) {
    asm volatile(
        "mma.sync.aligned.m16n8k8.row.col.f32.tf32.tf32.f32 "
        "{%0,%1,%2,%3}, {%4,%5,%6,%7}, {%8,%9}, {%0,%1,%2,%3};"
        : "+f"(d0), "+f"(d1), "+f"(d2), "+f"(d3)
        : "r"(a0), "r"(a1), "r"(a2), "r"(a3), "r"(b0), "r"(b1));
}
__device__ __forceinline__ void mma16(float& d0, float& d1, float& d2, float& d3,
                                      uint32_t a0, uint32_t a1, uint32_t a2, uint32_t a3,
                                      uint32_t b0, uint32_t b1) {
    asm volatile(
        "mma.sync.aligned.m16n8k16.row.col.f32.bf16.bf16.f32 "
        "{%0,%1,%2,%3}, {%4,%5,%6,%7}, {%8,%9}, {%0,%1,%2,%3};"
        : "+f"(d0), "+f"(d1), "+f"(d2), "+f"(d3)
        : "r"(a0), "r"(a1), "r"(a2), "r"(a3), "r"(b0), "r"(b1));
}
__device__ __forceinline__ void ldm4(uint32_t& r0, uint32_t& r1, uint32_t& r2, uint32_t& r3,
                                     uint32_t addr) {
    asm volatile("ldmatrix.sync.aligned.m8n8.x4.shared.b16 {%0,%1,%2,%3}, [%4];"
                 : "=r"(r0), "=r"(r1), "=r"(r2), "=r"(r3) : "r"(addr));
}
__device__ __forceinline__ uint32_t smem_u32(const void* p) {
    uint32_t a;
    asm("{ .reg .u64 t; cvta.to.shared.u64 t, %1; cvt.u32.u64 %0, t; }" : "=r"(a) : "l"(p));
    return a;
}
__device__ __forceinline__ void cpasync16(uint32_t dst, const void* src, int ssz) {
    asm volatile("cp.async.cg.shared.global [%0], [%1], 16, %2;"
                 :: "r"(dst), "l"(src), "r"(ssz) : "memory");
}

// ---------------- device scratch ----------------
__device__ int   g_is64;
__device__ int   g_pcounts[MAXCB * NOS];
__device__ int   g_counts[NOS];
__device__ int   g_base[NOS];
__device__ int   g_cursor[NOS];
__device__ int   g_total;
__device__ unsigned g_done;
__device__ int   g_order[PADN];
__device__ float g_partial[MAXNB];

// ---------------- count (self-detects int64 vs int32) ----------------
__global__ void k_count(const void* sp, int n) {
    __shared__ int h[NOS];
    __shared__ int bad;
    const int t = threadIdx.x;
    if (t < NOS) h[t] = 0;
    if (t == 0) bad = 0;
    __syncthreads();
    int lim = (n / 2 < 512) ? (n / 2) : 512;
    for (int i = t; i < lim; i += 256)
        if (((const ull*)sp)[i] >= 4ull) bad = 1;   // int32 data: hi word = next value
    __syncthreads();
    const int is64 = !bad;
    int i = blockIdx.x * 256 + t;
    if (i < n) {
        int s = is64 ? (int)((const long long*)sp)[i] : ((const int*)sp)[i];
        atomicAdd(&h[s], 1);
    }
    __syncthreads();
    if (t < NOS) g_pcounts[blockIdx.x * NOS + t] = h[t];
    if (t == 0 && blockIdx.x == 0) g_is64 = is64;
}

// ---------------- offsets: parallel partial-sum + bases ----------------
__global__ void k_offsets(int nb) {
    __shared__ int acc[128];
    const int t = threadIdx.x;
    const int s = t & 3, str = t >> 2;
    int c = 0;
    for (int b = str; b < nb; b += 32) c += g_pcounts[b * NOS + s];
    acc[t] = c;
    __syncthreads();
    if (t < 4) {
        int tot = 0;
#pragma unroll
        for (int j = t; j < 128; j += 4) tot += acc[j];
        g_counts[t] = tot;
    }
    __syncthreads();
    if (t == 0) {
        int base = 0;
#pragma unroll
        for (int s2 = 0; s2 < NOS; s2++) {
            g_base[s2]   = base;
            g_cursor[s2] = base;
            base += ((g_counts[s2] + TM - 1) / TM) * TM;
        }
        g_total = base;
        g_done  = 0u;
    }
}

// ---------------- scatter ----------------
__global__ void k_scatter(const void* sp, int n) {
    __shared__ int h[NOS];
    __shared__ int basebuf[NOS];
    const int t = threadIdx.x;
    if (t < NOS) h[t] = 0;
    __syncthreads();
    const int is64 = g_is64;
    int i = blockIdx.x * 256 + t;
    int s = 0, r = 0;
    bool valid = (i < n);
    if (valid) {
        s = is64 ? (int)((const long long*)sp)[i] : ((const int*)sp)[i];
        r = atomicAdd(&h[s], 1);
    }
    __syncthreads();
    if (t < NOS && h[t] > 0) basebuf[t] = atomicAdd(&g_cursor[t], h[t]);
    __syncthreads();
    if (valid) g_order[basebuf[s] + r] = i;
}

// ---------------- fused MLP: cp.async staging + tf32/bf16 HMMA ----------
__global__ void __launch_bounds__(128, 2)
k_mlp(const float* __restrict__ desc,
      const float* __restrict__ W0, const float* __restrict__ b0,
      const float* __restrict__ W1, const float* __restrict__ b1,
      const float* __restrict__ W2, const float* __restrict__ b2,
      float* __restrict__ out)
{
    extern __shared__ char smc[];
    const int t = threadIdx.x, wid = t >> 5, lane = t & 31;
    const int gid = lane >> 2, tid = lane & 3;
    const int tile0 = blockIdx.x * TM;

    float*         sS  = (float*)(smc + OFF_S);            // [128][132] fp32/tf32
    uint32_t*      sW0 = (uint32_t*)(smc + OFF_W0);        // [k=128][40] tf32
    __nv_bfloat16* sH  = (__nv_bfloat16*)(smc + OFF_H);    // [128][40]
    __nv_bfloat16* sW1 = (__nv_bfloat16*)(smc + OFF_W1);   // [c=32][40]
    float* vb0 = (float*)(smc + OFF_B0);
    float* vb1 = (float*)(smc + OFF_B1);
    float* vw2 = (float*)(smc + OFF_W2);
    float* vb2 = (float*)(smc + OFF_B2);
    int*   sidx = (int*)(smc + OFF_SIDX);
    float* sred = (float*)(smc + OFF_SRED);
    const uint32_t sSu = smem_u32(sS);

    if (tile0 < g_total) {
        int sp = 0;
#pragma unroll
        for (int s = 1; s < NOS; s++) if (tile0 >= g_base[s]) sp = s;
        const int cnt = g_counts[sp], segb = g_base[sp];

        // ---- issue all 32 desc-row cp.asyncs per thread first (deep MLP) ----
        const int local = tile0 + t - segb;
        const int myidx = (local < cnt) ? g_order[tile0 + t] : -1;
        sidx[t] = myidx;
#pragma unroll
        for (int r = 0; r < 32; r++) {
            int row = wid * 32 + r;
            int idx = __shfl_sync(0xffffffffu, myidx, r);
            const float* src = desc + (size_t)(idx < 0 ? 0 : idx) * IN + lane * 4;
            int ssz = (idx < 0) ? 0 : 16;
            cpasync16(sSu + (row * 132 + lane * 4) * 4, src, ssz);
        }

        // ---- stage weights while cp.asyncs stream ----
        {
            const float4* w4 = (const float4*)(W0 + sp * IN * H1);
#pragma unroll
            for (int e = t; e < IN * H1 / 4; e += 128) {
                int k = e >> 3, c = (e & 7) * 4;
                float4 v = w4[e];
                uint32_t* dst = sW0 + k * 40 + c;
                dst[0] = f2tf32(v.x); dst[1] = f2tf32(v.y);
                dst[2] = f2tf32(v.z); dst[3] = f2tf32(v.w);
            }
        }
        {
            const float4* w4 = (const float4*)(W1 + sp * H1 * H2);
#pragma unroll
            for (int e = t; e < H1 * H2 / 4; e += 128) {
                int k = e >> 3, c = (e & 7) * 4;
                float4 v = w4[e];
                sW1[(c + 0) * 40 + k] = __float2bfloat16_rn(v.x);
                sW1[(c + 1) * 40 + k] = __float2bfloat16_rn(v.y);
                sW1[(c + 2) * 40 + k] = __float2bfloat16_rn(v.z);
                sW1[(c + 3) * 40 + k] = __float2bfloat16_rn(v.w);
            }
        }
        if (t < H1) vb0[t] = b0[sp * H1 + t];
        if (t < H2) { vb1[t] = b1[sp * H2 + t]; vw2[t] = W2[sp * H2 + t]; }
        if (t == 0) vb2[0] = b2[sp];

        asm volatile("cp.async.wait_all;" ::: "memory");
        __syncthreads();

        const int wbase = wid * 32;
        float d[2][4][4];
#pragma unroll
        for (int mt = 0; mt < 2; mt++)
#pragma unroll
            for (int nt = 0; nt < 4; nt++)
#pragma unroll
                for (int i = 0; i < 4; i++) d[mt][nt][i] = 0.f;

        // -------- layer 0: [128x128] @ [128x32] tf32, 16 k8-steps --------
#pragma unroll
        for (int kk = 0; kk < 16; kk++) {
            const int k0 = kk * 8;
            uint32_t af[2][4];
#pragma unroll
            for (int mt = 0; mt < 2; mt++) {
                const float* ab = sS + (wbase + mt * 16 + gid) * 132 + k0 + tid;
                af[mt][0] = f2tf32(ab[0]);
                af[mt][1] = f2tf32(ab[8 * 132]);
                af[mt][2] = f2tf32(ab[4]);
                af[mt][3] = f2tf32(ab[8 * 132 + 4]);
            }
#pragma unroll
            for (int nt = 0; nt < 4; nt++) {
                const uint32_t* bb = sW0 + (k0 + tid) * 40 + nt * 8 + gid;
                uint32_t b0f = bb[0], b1f = bb[4 * 40];
                mma8(d[0][nt][0], d[0][nt][1], d[0][nt][2], d[0][nt][3],
                     af[0][0], af[0][1], af[0][2], af[0][3], b0f, b1f);
                mma8(d[1][nt][0], d[1][nt][1], d[1][nt][2], d[1][nt][3],
                     af[1][0], af[1][1], af[1][2], af[1][3], b0f, b1f);
            }
        }

        // -------- epilogue 0: bias + tanh -> bf16 -> sH --------
#pragma unroll
        for (int mt = 0; mt < 2; mt++) {
            int R0 = wbase + mt * 16 + gid;
#pragma unroll
            for (int nt = 0; nt < 4; nt++) {
                int c0 = nt * 8 + 2 * tid;
                *(uint32_t*)(sH + R0 * 40 + c0) =
                    packbf2(fast_tanh(d[mt][nt][0] + vb0[c0]),
                            fast_tanh(d[mt][nt][1] + vb0[c0 + 1]));
                *(uint32_t*)(sH + (R0 + 8) * 40 + c0) =
                    packbf2(fast_tanh(d[mt][nt][2] + vb0[c0]),
                            fast_tanh(d[mt][nt][3] + vb0[c0 + 1]));
                d[mt][nt][0] = 0.f; d[mt][nt][1] = 0.f;
                d[mt][nt][2] = 0.f; d[mt][nt][3] = 0.f;
            }
        }
        __syncwarp();

        // -------- layer 1: [128x32] @ [32x32] bf16, 2 k16-steps --------
        const uint32_t hAddr = smem_u32(sH);
        const int lrow = ((lane >> 3) & 1) * 8 + (lane & 7);
        const int lcol = (lane >> 4) * 8;
#pragma unroll
        for (int kk = 0; kk < 2; kk++) {
            const int k0 = kk * 16;
            uint32_t af[2][4];
#pragma unroll
            for (int mt = 0; mt < 2; mt++)
                ldm4(af[mt][0], af[mt][1], af[mt][2], af[mt][3],
                     hAddr + ((wbase + mt * 16 + lrow) * 40 + k0 + lcol) * 2);
#pragma unroll
            for (int nt = 0; nt < 4; nt++) {
                const __nv_bfloat16* bb = sW1 + (nt * 8 + gid) * 40 + k0 + 2 * tid;
                uint32_t b0f = *(const uint32_t*)bb;
                uint32_t b1f = *(const uint32_t*)(bb + 8);
                mma16(d[0][nt][0], d[0][nt][1], d[0][nt][2], d[0][nt][3],
                      af[0][0], af[0][1], af[0][2], af[0][3], b0f, b1f);
                mma16(d[1][nt][0], d[1][nt][1], d[1][nt][2], d[1][nt][3],
                      af[1][0], af[1][1], af[1][2], af[1][3], b0f, b1f);
            }
        }

        // -------- epilogue 1: bias + tanh + W2 dot --------
        {
            float p[4] = {0.f, 0.f, 0.f, 0.f};
#pragma unroll
            for (int mt = 0; mt < 2; mt++)
#pragma unroll
                for (int nt = 0; nt < 4; nt++) {
                    int c0 = nt * 8 + 2 * tid;
                    p[mt * 2 + 0] += fast_tanh(d[mt][nt][0] + vb1[c0])     * vw2[c0];
                    p[mt * 2 + 0] += fast_tanh(d[mt][nt][1] + vb1[c0 + 1]) * vw2[c0 + 1];
                    p[mt * 2 + 1] += fast_tanh(d[mt][nt][2] + vb1[c0])     * vw2[c0];
                    p[mt * 2 + 1] += fast_tanh(d[mt][nt][3] + vb1[c0 + 1]) * vw2[c0 + 1];
                }
#pragma unroll
            for (int i = 0; i < 4; i++) {
                p[i] += __shfl_xor_sync(0xffffffffu, p[i], 1);
                p[i] += __shfl_xor_sync(0xffffffffu, p[i], 2);
            }
            if (tid == 0) {
                float bb2 = vb2[0];
#pragma unroll
                for (int mt = 0; mt < 2; mt++)
#pragma unroll
                    for (int j = 0; j < 2; j++) {
                        int R = wbase + mt * 16 + j * 8 + gid;
                        sred[R] = (sidx[R] >= 0) ? (p[mt * 2 + j] + bb2) : 0.f;
                    }
            }
        }
        __syncthreads();

        if (t < 64) sred[t] += sred[t + 64];
        __syncthreads();
        if (t < 32) {
            float v = sred[t] + sred[t + 32];
#pragma unroll
            for (int o = 16; o > 0; o >>= 1) v += __shfl_down_sync(0xffffffffu, v, o);
            if (t == 0) g_partial[blockIdx.x] = v;
        }
    } else {
        if (t == 0) g_partial[blockIdx.x] = 0.f;
    }

    // -------- last-block deterministic final reduction --------
    __shared__ int slast;
    __syncthreads();
    if (t == 0) {
        __threadfence();
        unsigned prev = atomicAdd(&g_done, 1u);
        slast = (prev + 1 == gridDim.x);
    }
    __syncthreads();
    if (slast) {
        float v = 0.f;
        for (int i = t; i < (int)gridDim.x; i += 128) v += g_partial[i];
        sred[t] = v;
        __syncthreads();
        if (t < 64) sred[t] += sred[t + 64];
        __syncthreads();
        if (t < 32) {
            float x = sred[t] + sred[t + 32];
#pragma unroll
            for (int o = 16; o > 0; o >>= 1) x += __shfl_down_sync(0xffffffffu, x, o);
            if (t == 0) out[0] = x;
        }
    }
}

// ---------------- launcher ----------------
extern "C" void kernel_launch(void* const* d_in, const int* in_sizes, int n_in,
                              void* d_out, int out_size)
{
    const float* desc    = (const float*)d_in[0];
    const void*  species = d_in[1];
    const float* W0 = (const float*)d_in[2];
    const float* b0 = (const float*)d_in[3];
    const float* W1 = (const float*)d_in[4];
    const float* b1 = (const float*)d_in[5];
    const float* W2 = (const float*)d_in[6];
    const float* b2 = (const float*)d_in[7];

    int n = in_sizes[1];
    if (n > MAXN) n = MAXN;

    int nb_atoms = (n + 255) / 256;
    if (nb_atoms > MAXCB) nb_atoms = MAXCB;
    int nb_mlp = (n + TM - 1) / TM + NOS;
    if (nb_mlp > MAXNB) nb_mlp = MAXNB;

    cudaFuncSetAttribute(k_mlp, cudaFuncAttributeMaxDynamicSharedMemorySize, SMEM_BYTES);

    k_count<<<nb_atoms, 256>>>(species, n);
    k_offsets<<<1, 128>>>(nb_atoms);
    k_scatter<<<nb_atoms, 256>>>(species, n);
    k_mlp<<<nb_mlp, 128, SMEM_BYTES>>>(desc, W0, b0, W1, b1, W2, b2, (float*)d_out);
}

// round 7
// speedup vs baseline: 1.3003x; 1.3003x over previous
#include <cuda_runtime.h>
#include <cuda_bf16.h>
#include <cstdint>

#define MAXN   500000
#define IN     128
#define H1     32
#define H2     32
#define NOS    4
#define TM     128
#define MAXNB  3912
#define PADN   (MAXNB * TM)
#define MAXCB  1954                  // ceil(MAXN/256)

typedef unsigned long long ull;

// ---- smem byte offsets (k_mlp). h tile ALIASES the dead A tile. ----
#define OFF_A     0          // A bf16 [128][136] = 34816 ; h bf16 [128][40] aliased here
#define OFF_W0    34816      // W0T bf16 [c=32][k=136pad] = 8704
#define OFF_W1    43520      // W1T bf16 [c=32][k=40pad]  = 2560
#define OFF_B0    46080
#define OFF_B1    46208
#define OFF_W2    46336
#define OFF_B2    46464
#define OFF_SIDX  46480      // 128 ints
#define OFF_SRED  46992      // 128 floats
#define SMEM_BYTES 47616

__device__ __forceinline__ float fast_tanh(float x) {
    float e, r;
    asm("ex2.approx.f32 %0, %1;" : "=f"(e) : "f"(x * 2.885390081777927f));
    asm("rcp.approx.f32 %0, %1;" : "=f"(r) : "f"(e + 1.0f));
    return fmaf(-2.0f, r, 1.0f);
}
__device__ __forceinline__ uint32_t packbf2(float lo, float hi) {
    __nv_bfloat162 p = __floats2bfloat162_rn(lo, hi);
    return *(uint32_t*)&p;
}
__device__ __forceinline__ void mma16(float& d0, float& d1, float& d2, float& d3,
                                      uint32_t a0, uint32_t a1, uint32_t a2, uint32_t a3,
                                      uint32_t b0, uint32_t b1) {
    asm volatile(
        "mma.sync.aligned.m16n8k16.row.col.f32.bf16.bf16.f32 "
        "{%0,%1,%2,%3}, {%4,%5,%6,%7}, {%8,%9}, {%0,%1,%2,%3};"
        : "+f"(d0), "+f"(d1), "+f"(d2), "+f"(d3)
        : "r"(a0), "r"(a1), "r"(a2), "r"(a3), "r"(b0), "r"(b1));
}
__device__ __forceinline__ void ldm4(uint32_t& r0, uint32_t& r1, uint32_t& r2, uint32_t& r3,
                                     uint32_t addr) {
    asm volatile("ldmatrix.sync.aligned.m8n8.x4.shared.b16 {%0,%1,%2,%3}, [%4];"
                 : "=r"(r0), "=r"(r1), "=r"(r2), "=r"(r3) : "r"(addr));
}
__device__ __forceinline__ uint32_t smem_u32(const void* p) {
    uint32_t a;
    asm("{ .reg .u64 t; cvta.to.shared.u64 t, %1; cvt.u32.u64 %0, t; }" : "=r"(a) : "l"(p));
    return a;
}

// ---------------- device scratch ----------------
__device__ int   g_is64;
__device__ int   g_pcounts[MAXCB * NOS];
__device__ int   g_counts[NOS];
__device__ int   g_base[NOS];
__device__ int   g_cursor[NOS];
__device__ int   g_total;
__device__ unsigned g_done;
__device__ int   g_order[PADN];
__device__ float g_partial[MAXNB];

// ---------------- count (self-detects int64 vs int32) ----------------
__global__ void k_count(const void* sp, int n) {
    __shared__ int h[NOS];
    __shared__ int bad;
    const int t = threadIdx.x;
    if (t < NOS) h[t] = 0;
    if (t == 0) bad = 0;
    __syncthreads();
    int lim = (n / 2 < 512) ? (n / 2) : 512;
    for (int i = t; i < lim; i += 256)
        if (((const ull*)sp)[i] >= 4ull) bad = 1;
    __syncthreads();
    const int is64 = !bad;
    int i = blockIdx.x * 256 + t;
    if (i < n) {
        int s = is64 ? (int)((const long long*)sp)[i] : ((const int*)sp)[i];
        atomicAdd(&h[s], 1);
    }
    __syncthreads();
    if (t < NOS) g_pcounts[blockIdx.x * NOS + t] = h[t];
    if (t == 0 && blockIdx.x == 0) g_is64 = is64;
}

// ---------------- offsets ----------------
__global__ void k_offsets(int nb) {
    __shared__ int acc[128];
    const int t = threadIdx.x;
    const int s = t & 3, str = t >> 2;
    int c = 0;
    for (int b = str; b < nb; b += 32) c += g_pcounts[b * NOS + s];
    acc[t] = c;
    __syncthreads();
    if (t < 4) {
        int tot = 0;
#pragma unroll
        for (int j = t; j < 128; j += 4) tot += acc[j];
        g_counts[t] = tot;
    }
    __syncthreads();
    if (t == 0) {
        int base = 0;
#pragma unroll
        for (int s2 = 0; s2 < NOS; s2++) {
            g_base[s2]   = base;
            g_cursor[s2] = base;
            base += ((g_counts[s2] + TM - 1) / TM) * TM;
        }
        g_total = base;
        g_done  = 0u;
    }
}

// ---------------- scatter ----------------
__global__ void k_scatter(const void* sp, int n) {
    __shared__ int h[NOS];
    __shared__ int basebuf[NOS];
    const int t = threadIdx.x;
    if (t < NOS) h[t] = 0;
    __syncthreads();
    const int is64 = g_is64;
    int i = blockIdx.x * 256 + t;
    int s = 0, r = 0;
    bool valid = (i < n);
    if (valid) {
        s = is64 ? (int)((const long long*)sp)[i] : ((const int*)sp)[i];
        r = atomicAdd(&h[s], 1);
    }
    __syncthreads();
    if (t < NOS && h[t] > 0) basebuf[t] = atomicAdd(&g_cursor[t], h[t]);
    __syncthreads();
    if (valid) g_order[basebuf[s] + r] = i;
}

// ---------------- bf16 HMMA fused MLP + fused final reduction ----------
__global__ void __launch_bounds__(128, 3)
k_mlp(const float* __restrict__ desc,
      const float* __restrict__ W0, const float* __restrict__ b0,
      const float* __restrict__ W1, const float* __restrict__ b1,
      const float* __restrict__ W2, const float* __restrict__ b2,
      float* __restrict__ out)
{
    extern __shared__ char smc[];
    const int t = threadIdx.x, wid = t >> 5, lane = t & 31;
    const int gid = lane >> 2, tid = lane & 3;
    const int tile0 = blockIdx.x * TM;

    __nv_bfloat16* sA  = (__nv_bfloat16*)(smc + OFF_A);    // [128][136]
    __nv_bfloat16* sH  = (__nv_bfloat16*)(smc + OFF_A);    // [128][40] (alias)
    __nv_bfloat16* sW0 = (__nv_bfloat16*)(smc + OFF_W0);   // [c=32][136]
    __nv_bfloat16* sW1 = (__nv_bfloat16*)(smc + OFF_W1);   // [c=32][40]
    float* vb0 = (float*)(smc + OFF_B0);
    float* vb1 = (float*)(smc + OFF_B1);
    float* vw2 = (float*)(smc + OFF_W2);
    float* vb2 = (float*)(smc + OFF_B2);
    int*   sidx = (int*)(smc + OFF_SIDX);
    float* sred = (float*)(smc + OFF_SRED);

    if (tile0 < g_total) {
        int sp = 0;
#pragma unroll
        for (int s = 1; s < NOS; s++) if (tile0 >= g_base[s]) sp = s;
        const int cnt = g_counts[sp], segb = g_base[sp];

        // ---- stage weights ----
        {
            const float4* w4 = (const float4*)(W0 + sp * IN * H1);
#pragma unroll
            for (int e = t; e < IN * H1 / 4; e += 128) {
                int k = e >> 3, c = (e & 7) * 4;
                float4 v = w4[e];
                sW0[(c + 0) * 136 + k] = __float2bfloat16_rn(v.x);
                sW0[(c + 1) * 136 + k] = __float2bfloat16_rn(v.y);
                sW0[(c + 2) * 136 + k] = __float2bfloat16_rn(v.z);
                sW0[(c + 3) * 136 + k] = __float2bfloat16_rn(v.w);
            }
        }
        {
            const float4* w4 = (const float4*)(W1 + sp * H1 * H2);
#pragma unroll
            for (int e = t; e < H1 * H2 / 4; e += 128) {
                int k = e >> 3, c = (e & 7) * 4;
                float4 v = w4[e];
                sW1[(c + 0) * 40 + k] = __float2bfloat16_rn(v.x);
                sW1[(c + 1) * 40 + k] = __float2bfloat16_rn(v.y);
                sW1[(c + 2) * 40 + k] = __float2bfloat16_rn(v.z);
                sW1[(c + 3) * 40 + k] = __float2bfloat16_rn(v.w);
            }
        }
        if (t < H1) vb0[t] = b0[sp * H1 + t];
        if (t < H2) { vb1[t] = b1[sp * H2 + t]; vw2[t] = W2[sp * H2 + t]; }
        if (t == 0) vb2[0] = b2[sp];

        // ---- stage desc tile: 8-deep front-batched LDG.128 per group ----
        const int local = tile0 + t - segb;
        const int myidx = (local < cnt) ? g_order[tile0 + t] : -1;
        sidx[t] = myidx;
#pragma unroll
        for (int rr = 0; rr < 4; rr++) {
            int idxs[8];
#pragma unroll
            for (int j = 0; j < 8; j++)
                idxs[j] = __shfl_sync(0xffffffffu, myidx, rr * 8 + j);
            float4 v[8];
#pragma unroll
            for (int j = 0; j < 8; j++) {
                v[j] = make_float4(0.f, 0.f, 0.f, 0.f);
                if (idxs[j] >= 0)
                    v[j] = *(const float4*)(desc + (size_t)idxs[j] * IN + lane * 4);
            }
#pragma unroll
            for (int j = 0; j < 8; j++) {
                int row = wid * 32 + rr * 8 + j;
                uint2 u;
                u.x = packbf2(v[j].x, v[j].y);
                u.y = packbf2(v[j].z, v[j].w);
                *(uint2*)(sA + row * 136 + lane * 4) = u;
            }
        }
        __syncthreads();

        const int wbase = wid * 32;
        const uint32_t aAddr = smem_u32(sA);
        const int lrow = ((lane >> 3) & 1) * 8 + (lane & 7);
        const int lcol = (lane >> 4) * 8;

        float d[2][4][4];
#pragma unroll
        for (int mt = 0; mt < 2; mt++)
#pragma unroll
            for (int nt = 0; nt < 4; nt++)
#pragma unroll
                for (int i = 0; i < 4; i++) d[mt][nt][i] = 0.f;

        // -------- layer 0: [128x128] @ [128x32] bf16, 8 k16-steps --------
#pragma unroll
        for (int kk = 0; kk < 8; kk++) {
            const int k0 = kk * 16;
            uint32_t af[2][4];
#pragma unroll
            for (int mt = 0; mt < 2; mt++)
                ldm4(af[mt][0], af[mt][1], af[mt][2], af[mt][3],
                     aAddr + ((wbase + mt * 16 + lrow) * 136 + k0 + lcol) * 2);
#pragma unroll
            for (int nt = 0; nt < 4; nt++) {
                const __nv_bfloat16* bb = sW0 + (nt * 8 + gid) * 136 + k0 + 2 * tid;
                uint32_t b0f = *(const uint32_t*)bb;
                uint32_t b1f = *(const uint32_t*)(bb + 8);
                mma16(d[0][nt][0], d[0][nt][1], d[0][nt][2], d[0][nt][3],
                      af[0][0], af[0][1], af[0][2], af[0][3], b0f, b1f);
                mma16(d[1][nt][0], d[1][nt][1], d[1][nt][2], d[1][nt][3],
                      af[1][0], af[1][1], af[1][2], af[1][3], b0f, b1f);
            }
        }

        // A fully consumed by all warps before h overwrites it (aliasing)
        __syncthreads();

        // -------- epilogue 0: bias + tanh -> bf16 -> sH (aliased) --------
#pragma unroll
        for (int mt = 0; mt < 2; mt++) {
            int R0 = wbase + mt * 16 + gid;
#pragma unroll
            for (int nt = 0; nt < 4; nt++) {
                int c0 = nt * 8 + 2 * tid;
                *(uint32_t*)(sH + R0 * 40 + c0) =
                    packbf2(fast_tanh(d[mt][nt][0] + vb0[c0]),
                            fast_tanh(d[mt][nt][1] + vb0[c0 + 1]));
                *(uint32_t*)(sH + (R0 + 8) * 40 + c0) =
                    packbf2(fast_tanh(d[mt][nt][2] + vb0[c0]),
                            fast_tanh(d[mt][nt][3] + vb0[c0 + 1]));
                d[mt][nt][0] = 0.f; d[mt][nt][1] = 0.f;
                d[mt][nt][2] = 0.f; d[mt][nt][3] = 0.f;
            }
        }
        __syncwarp();

        // -------- layer 1: [128x32] @ [32x32] bf16, 2 k16-steps --------
#pragma unroll
        for (int kk = 0; kk < 2; kk++) {
            const int k0 = kk * 16;
            uint32_t af[2][4];
#pragma unroll
            for (int mt = 0; mt < 2; mt++)
                ldm4(af[mt][0], af[mt][1], af[mt][2], af[mt][3],
                     aAddr + ((wbase + mt * 16 + lrow) * 40 + k0 + lcol) * 2);
#pragma unroll
            for (int nt = 0; nt < 4; nt++) {
                const __nv_bfloat16* bb = sW1 + (nt * 8 + gid) * 40 + k0 + 2 * tid;
                uint32_t b0f = *(const uint32_t*)bb;
                uint32_t b1f = *(const uint32_t*)(bb + 8);
                mma16(d[0][nt][0], d[0][nt][1], d[0][nt][2], d[0][nt][3],
                      af[0][0], af[0][1], af[0][2], af[0][3], b0f, b1f);
                mma16(d[1][nt][0], d[1][nt][1], d[1][nt][2], d[1][nt][3],
                      af[1][0], af[1][1], af[1][2], af[1][3], b0f, b1f);
            }
        }

        // -------- epilogue 1: bias + tanh + W2 dot --------
        {
            float p[4] = {0.f, 0.f, 0.f, 0.f};
#pragma unroll
            for (int mt = 0; mt < 2; mt++)
#pragma unroll
                for (int nt = 0; nt < 4; nt++) {
                    int c0 = nt * 8 + 2 * tid;
                    p[mt * 2 + 0] += fast_tanh(d[mt][nt][0] + vb1[c0])     * vw2[c0];
                    p[mt * 2 + 0] += fast_tanh(d[mt][nt][1] + vb1[c0 + 1]) * vw2[c0 + 1];
                    p[mt * 2 + 1] += fast_tanh(d[mt][nt][2] + vb1[c0])     * vw2[c0];
                    p[mt * 2 + 1] += fast_tanh(d[mt][nt][3] + vb1[c0 + 1]) * vw2[c0 + 1];
                }
#pragma unroll
            for (int i = 0; i < 4; i++) {
                p[i] += __shfl_xor_sync(0xffffffffu, p[i], 1);
                p[i] += __shfl_xor_sync(0xffffffffu, p[i], 2);
            }
            if (tid == 0) {
                float bb2 = vb2[0];
#pragma unroll
                for (int mt = 0; mt < 2; mt++)
#pragma unroll
                    for (int j = 0; j < 2; j++) {
                        int R = wbase + mt * 16 + j * 8 + gid;
                        sred[R] = (sidx[R] >= 0) ? (p[mt * 2 + j] + bb2) : 0.f;
                    }
            }
        }
        __syncthreads();

        if (t < 64) sred[t] += sred[t + 64];
        __syncthreads();
        if (t < 32) {
            float v = sred[t] + sred[t + 32];
#pragma unroll
            for (int o = 16; o > 0; o >>= 1) v += __shfl_down_sync(0xffffffffu, v, o);
            if (t == 0) g_partial[blockIdx.x] = v;
        }
    } else {
        if (t == 0) g_partial[blockIdx.x] = 0.f;
    }

    // -------- last-block deterministic final reduction --------
    __shared__ int slast;
    __syncthreads();
    if (t == 0) {
        __threadfence();
        unsigned prev = atomicAdd(&g_done, 1u);
        slast = (prev + 1 == gridDim.x);
    }
    __syncthreads();
    if (slast) {
        float v = 0.f;
        for (int i = t; i < (int)gridDim.x; i += 128) v += g_partial[i];
        sred[t] = v;
        __syncthreads();
        if (t < 64) sred[t] += sred[t + 64];
        __syncthreads();
        if (t < 32) {
            float x = sred[t] + sred[t + 32];
#pragma unroll
            for (int o = 16; o > 0; o >>= 1) x += __shfl_down_sync(0xffffffffu, x, o);
            if (t == 0) out[0] = x;
        }
    }
}

// ---------------- launcher ----------------
extern "C" void kernel_launch(void* const* d_in, const int* in_sizes, int n_in,
                              void* d_out, int out_size)
{
    const float* desc    = (const float*)d_in[0];
    const void*  species = d_in[1];
    const float* W0 = (const float*)d_in[2];
    const float* b0 = (const float*)d_in[3];
    const float* W1 = (const float*)d_in[4];
    const float* b1 = (const float*)d_in[5];
    const float* W2 = (const float*)d_in[6];
    const float* b2 = (const float*)d_in[7];

    int n = in_sizes[1];
    if (n > MAXN) n = MAXN;

    int nb_atoms = (n + 255) / 256;
    if (nb_atoms > MAXCB) nb_atoms = MAXCB;
    int nb_mlp = (n + TM - 1) / TM + NOS;
    if (nb_mlp > MAXNB) nb_mlp = MAXNB;

    cudaFuncSetAttribute(k_mlp, cudaFuncAttributeMaxDynamicSharedMemorySize, SMEM_BYTES);

    k_count<<<nb_atoms, 256>>>(species, n);
    k_offsets<<<1, 128>>>(nb_atoms);
    k_scatter<<<nb_atoms, 256>>>(species, n);
    k_mlp<<<nb_mlp, 128, SMEM_BYTES>>>(desc, W0, b0, W1, b1, W2, b2, (float*)d_out);
}

// round 8
// speedup vs baseline: 1.4211x; 1.0929x over previous
#include <cuda_runtime.h>
#include <cuda_bf16.h>
#include <cstdint>

#define MAXN   500000
#define IN     128
#define H1     32
#define H2     32
#define NOS    4
#define TM     256
#define MAXNB  1958                  // ceil(MAXN/256) + NOS
#define PADN   (MAXNB * TM)
#define MAXCB  1954                  // ceil(MAXN/256)

typedef unsigned long long ull;

// ---- smem byte offsets (k_mlp). h tile ALIASES the dead A tile. ----
#define OFF_A     0          // A bf16 [256][136] = 69632 ; h bf16 [256][40] aliased
#define OFF_W0    69632      // W0T bf16 [c=32][k=136pad] = 8704
#define OFF_W1    78336      // W1T bf16 [c=32][k=40pad]  = 2560
#define OFF_B0    80896
#define OFF_B1    81024
#define OFF_W2    81152
#define OFF_B2    81280
#define OFF_SIDX  81296      // 256 ints
#define OFF_SRED  82320      // 256 floats
#define SMEM_BYTES 83456

__device__ __forceinline__ float fast_tanh(float x) {
    float e, r;
    asm("ex2.approx.f32 %0, %1;" : "=f"(e) : "f"(x * 2.885390081777927f));
    asm("rcp.approx.f32 %0, %1;" : "=f"(r) : "f"(e + 1.0f));
    return fmaf(-2.0f, r, 1.0f);
}
__device__ __forceinline__ uint32_t packbf2(float lo, float hi) {
    __nv_bfloat162 p = __floats2bfloat162_rn(lo, hi);
    return *(uint32_t*)&p;
}
__device__ __forceinline__ void mma16(float& d0, float& d1, float& d2, float& d3,
                                      uint32_t a0, uint32_t a1, uint32_t a2, uint32_t a3,
                                      uint32_t b0, uint32_t b1) {
    asm volatile(
        "mma.sync.aligned.m16n8k16.row.col.f32.bf16.bf16.f32 "
        "{%0,%1,%2,%3}, {%4,%5,%6,%7}, {%8,%9}, {%0,%1,%2,%3};"
        : "+f"(d0), "+f"(d1), "+f"(d2), "+f"(d3)
        : "r"(a0), "r"(a1), "r"(a2), "r"(a3), "r"(b0), "r"(b1));
}
__device__ __forceinline__ void ldm4(uint32_t& r0, uint32_t& r1, uint32_t& r2, uint32_t& r3,
                                     uint32_t addr) {
    asm volatile("ldmatrix.sync.aligned.m8n8.x4.shared.b16 {%0,%1,%2,%3}, [%4];"
                 : "=r"(r0), "=r"(r1), "=r"(r2), "=r"(r3) : "r"(addr));
}
__device__ __forceinline__ uint32_t smem_u32(const void* p) {
    uint32_t a;
    asm("{ .reg .u64 t; cvta.to.shared.u64 t, %1; cvt.u32.u64 %0, t; }" : "=r"(a) : "l"(p));
    return a;
}

// ---------------- device scratch ----------------
__device__ int   g_is64;
__device__ int   g_pcounts[MAXCB * NOS];
__device__ int   g_counts[NOS];
__device__ int   g_base[NOS];
__device__ int   g_cursor[NOS];
__device__ int   g_total;
__device__ unsigned g_done;
__device__ int   g_order[PADN];
__device__ float g_partial[MAXNB];

// ---------------- count (self-detects int64 vs int32) ----------------
__global__ void k_count(const void* sp, int n) {
    __shared__ int h[NOS];
    __shared__ int bad;
    const int t = threadIdx.x;
    if (t < NOS) h[t] = 0;
    if (t == 0) bad = 0;
    __syncthreads();
    int lim = (n / 2 < 512) ? (n / 2) : 512;
    for (int i = t; i < lim; i += 256)
        if (((const ull*)sp)[i] >= 4ull) bad = 1;
    __syncthreads();
    const int is64 = !bad;
    int i = blockIdx.x * 256 + t;
    if (i < n) {
        int s = is64 ? (int)((const long long*)sp)[i] : ((const int*)sp)[i];
        atomicAdd(&h[s], 1);
    }
    __syncthreads();
    if (t < NOS) g_pcounts[blockIdx.x * NOS + t] = h[t];
    if (t == 0 && blockIdx.x == 0) g_is64 = is64;
}

// ---------------- offsets ----------------
__global__ void k_offsets(int nb) {
    __shared__ int acc[128];
    const int t = threadIdx.x;
    const int s = t & 3, str = t >> 2;
    int c = 0;
    for (int b = str; b < nb; b += 32) c += g_pcounts[b * NOS + s];
    acc[t] = c;
    __syncthreads();
    if (t < 4) {
        int tot = 0;
#pragma unroll
        for (int j = t; j < 128; j += 4) tot += acc[j];
        g_counts[t] = tot;
    }
    __syncthreads();
    if (t == 0) {
        int base = 0;
#pragma unroll
        for (int s2 = 0; s2 < NOS; s2++) {
            g_base[s2]   = base;
            g_cursor[s2] = base;
            base += ((g_counts[s2] + TM - 1) / TM) * TM;
        }
        g_total = base;
        g_done  = 0u;
    }
}

// ---------------- scatter ----------------
__global__ void k_scatter(const void* sp, int n) {
    __shared__ int h[NOS];
    __shared__ int basebuf[NOS];
    const int t = threadIdx.x;
    if (t < NOS) h[t] = 0;
    __syncthreads();
    const int is64 = g_is64;
    int i = blockIdx.x * 256 + t;
    int s = 0, r = 0;
    bool valid = (i < n);
    if (valid) {
        s = is64 ? (int)((const long long*)sp)[i] : ((const int*)sp)[i];
        r = atomicAdd(&h[s], 1);
    }
    __syncthreads();
    if (t < NOS && h[t] > 0) basebuf[t] = atomicAdd(&g_cursor[t], h[t]);
    __syncthreads();
    if (valid) g_order[basebuf[s] + r] = i;
}

// ---------------- bf16 HMMA fused MLP, 256 atoms/CTA, 8 warps ----------
__global__ void __launch_bounds__(256, 2)
k_mlp(const float* __restrict__ desc,
      const float* __restrict__ W0, const float* __restrict__ b0,
      const float* __restrict__ W1, const float* __restrict__ b1,
      const float* __restrict__ W2, const float* __restrict__ b2,
      float* __restrict__ out)
{
    extern __shared__ char smc[];
    const int t = threadIdx.x, wid = t >> 5, lane = t & 31;
    const int gid = lane >> 2, tid = lane & 3;
    const int tile0 = blockIdx.x * TM;

    __nv_bfloat16* sA  = (__nv_bfloat16*)(smc + OFF_A);    // [256][136]
    __nv_bfloat16* sH  = (__nv_bfloat16*)(smc + OFF_A);    // [256][40] (alias)
    __nv_bfloat16* sW0 = (__nv_bfloat16*)(smc + OFF_W0);   // [c=32][136]
    __nv_bfloat16* sW1 = (__nv_bfloat16*)(smc + OFF_W1);   // [c=32][40]
    float* vb0 = (float*)(smc + OFF_B0);
    float* vb1 = (float*)(smc + OFF_B1);
    float* vw2 = (float*)(smc + OFF_W2);
    float* vb2 = (float*)(smc + OFF_B2);
    int*   sidx = (int*)(smc + OFF_SIDX);
    float* sred = (float*)(smc + OFF_SRED);

    if (tile0 < g_total) {
        int sp = 0;
#pragma unroll
        for (int s = 1; s < NOS; s++) if (tile0 >= g_base[s]) sp = s;
        const int cnt = g_counts[sp], segb = g_base[sp];

        // ---- stage weights ----
        {
            const float4* w4 = (const float4*)(W0 + sp * IN * H1);
#pragma unroll
            for (int e = t; e < IN * H1 / 4; e += 256) {
                int k = e >> 3, c = (e & 7) * 4;
                float4 v = w4[e];
                sW0[(c + 0) * 136 + k] = __float2bfloat16_rn(v.x);
                sW0[(c + 1) * 136 + k] = __float2bfloat16_rn(v.y);
                sW0[(c + 2) * 136 + k] = __float2bfloat16_rn(v.z);
                sW0[(c + 3) * 136 + k] = __float2bfloat16_rn(v.w);
            }
        }
        {
            const float4* w4 = (const float4*)(W1 + sp * H1 * H2);
#pragma unroll
            for (int e = t; e < H1 * H2 / 4; e += 256) {
                int k = e >> 3, c = (e & 7) * 4;
                float4 v = w4[e];
                sW1[(c + 0) * 40 + k] = __float2bfloat16_rn(v.x);
                sW1[(c + 1) * 40 + k] = __float2bfloat16_rn(v.y);
                sW1[(c + 2) * 40 + k] = __float2bfloat16_rn(v.z);
                sW1[(c + 3) * 40 + k] = __float2bfloat16_rn(v.w);
            }
        }
        if (t < H1) vb0[t] = b0[sp * H1 + t];
        if (t < H2) { vb1[t] = b1[sp * H2 + t]; vw2[t] = W2[sp * H2 + t]; }
        if (t == 0) vb2[0] = b2[sp];

        // ---- stage desc tile: 8-deep front-batched LDG.128 per group ----
        const int local = tile0 + t - segb;
        const int myidx = (local < cnt) ? g_order[tile0 + t] : -1;
        sidx[t] = myidx;
#pragma unroll
        for (int rr = 0; rr < 4; rr++) {
            int idxs[8];
#pragma unroll
            for (int j = 0; j < 8; j++)
                idxs[j] = __shfl_sync(0xffffffffu, myidx, rr * 8 + j);
            float4 v[8];
#pragma unroll
            for (int j = 0; j < 8; j++) {
                v[j] = make_float4(0.f, 0.f, 0.f, 0.f);
                if (idxs[j] >= 0)
                    v[j] = *(const float4*)(desc + (size_t)idxs[j] * IN + lane * 4);
            }
#pragma unroll
            for (int j = 0; j < 8; j++) {
                int row = wid * 32 + rr * 8 + j;
                uint2 u;
                u.x = packbf2(v[j].x, v[j].y);
                u.y = packbf2(v[j].z, v[j].w);
                *(uint2*)(sA + row * 136 + lane * 4) = u;
            }
        }
        __syncthreads();

        const int wbase = wid * 32;
        const uint32_t aAddr = smem_u32(sA);
        const int lrow = ((lane >> 3) & 1) * 8 + (lane & 7);
        const int lcol = (lane >> 4) * 8;

        float d[2][4][4];
#pragma unroll
        for (int mt = 0; mt < 2; mt++)
#pragma unroll
            for (int nt = 0; nt < 4; nt++)
#pragma unroll
                for (int i = 0; i < 4; i++) d[mt][nt][i] = 0.f;

        // -------- layer 0: [256x128] @ [128x32] bf16, 8 k16-steps --------
#pragma unroll
        for (int kk = 0; kk < 8; kk++) {
            const int k0 = kk * 16;
            uint32_t af[2][4];
#pragma unroll
            for (int mt = 0; mt < 2; mt++)
                ldm4(af[mt][0], af[mt][1], af[mt][2], af[mt][3],
                     aAddr + ((wbase + mt * 16 + lrow) * 136 + k0 + lcol) * 2);
#pragma unroll
            for (int nt = 0; nt < 4; nt++) {
                const __nv_bfloat16* bb = sW0 + (nt * 8 + gid) * 136 + k0 + 2 * tid;
                uint32_t b0f = *(const uint32_t*)bb;
                uint32_t b1f = *(const uint32_t*)(bb + 8);
                mma16(d[0][nt][0], d[0][nt][1], d[0][nt][2], d[0][nt][3],
                      af[0][0], af[0][1], af[0][2], af[0][3], b0f, b1f);
                mma16(d[1][nt][0], d[1][nt][1], d[1][nt][2], d[1][nt][3],
                      af[1][0], af[1][1], af[1][2], af[1][3], b0f, b1f);
            }
        }

        // A fully consumed by all warps before h overwrites it (aliasing)
        __syncthreads();

        // -------- epilogue 0: bias + tanh -> bf16 -> sH (aliased) --------
#pragma unroll
        for (int mt = 0; mt < 2; mt++) {
            int R0 = wbase + mt * 16 + gid;
#pragma unroll
            for (int nt = 0; nt < 4; nt++) {
                int c0 = nt * 8 + 2 * tid;
                *(uint32_t*)(sH + R0 * 40 + c0) =
                    packbf2(fast_tanh(d[mt][nt][0] + vb0[c0]),
                            fast_tanh(d[mt][nt][1] + vb0[c0 + 1]));
                *(uint32_t*)(sH + (R0 + 8) * 40 + c0) =
                    packbf2(fast_tanh(d[mt][nt][2] + vb0[c0]),
                            fast_tanh(d[mt][nt][3] + vb0[c0 + 1]));
                d[mt][nt][0] = 0.f; d[mt][nt][1] = 0.f;
                d[mt][nt][2] = 0.f; d[mt][nt][3] = 0.f;
            }
        }
        __syncwarp();

        // -------- layer 1: [256x32] @ [32x32] bf16, 2 k16-steps --------
#pragma unroll
        for (int kk = 0; kk < 2; kk++) {
            const int k0 = kk * 16;
            uint32_t af[2][4];
#pragma unroll
            for (int mt = 0; mt < 2; mt++)
                ldm4(af[mt][0], af[mt][1], af[mt][2], af[mt][3],
                     aAddr + ((wbase + mt * 16 + lrow) * 40 + k0 + lcol) * 2);
#pragma unroll
            for (int nt = 0; nt < 4; nt++) {
                const __nv_bfloat16* bb = sW1 + (nt * 8 + gid) * 40 + k0 + 2 * tid;
                uint32_t b0f = *(const uint32_t*)bb;
                uint32_t b1f = *(const uint32_t*)(bb + 8);
                mma16(d[0][nt][0], d[0][nt][1], d[0][nt][2], d[0][nt][3],
                      af[0][0], af[0][1], af[0][2], af[0][3], b0f, b1f);
                mma16(d[1][nt][0], d[1][nt][1], d[1][nt][2], d[1][nt][3],
                      af[1][0], af[1][1], af[1][2], af[1][3], b0f, b1f);
            }
        }

        // -------- epilogue 1: bias + tanh + W2 dot --------
        {
            float p[4] = {0.f, 0.f, 0.f, 0.f};
#pragma unroll
            for (int mt = 0; mt < 2; mt++)
#pragma unroll
                for (int nt = 0; nt < 4; nt++) {
                    int c0 = nt * 8 + 2 * tid;
                    p[mt * 2 + 0] += fast_tanh(d[mt][nt][0] + vb1[c0])     * vw2[c0];
                    p[mt * 2 + 0] += fast_tanh(d[mt][nt][1] + vb1[c0 + 1]) * vw2[c0 + 1];
                    p[mt * 2 + 1] += fast_tanh(d[mt][nt][2] + vb1[c0])     * vw2[c0];
                    p[mt * 2 + 1] += fast_tanh(d[mt][nt][3] + vb1[c0 + 1]) * vw2[c0 + 1];
                }
#pragma unroll
            for (int i = 0; i < 4; i++) {
                p[i] += __shfl_xor_sync(0xffffffffu, p[i], 1);
                p[i] += __shfl_xor_sync(0xffffffffu, p[i], 2);
            }
            if (tid == 0) {
                float bb2 = vb2[0];
#pragma unroll
                for (int mt = 0; mt < 2; mt++)
#pragma unroll
                    for (int j = 0; j < 2; j++) {
                        int R = wbase + mt * 16 + j * 8 + gid;
                        sred[R] = (sidx[R] >= 0) ? (p[mt * 2 + j] + bb2) : 0.f;
                    }
            }
        }
        __syncthreads();

        if (t < 128) sred[t] += sred[t + 128];
        __syncthreads();
        if (t < 64) sred[t] += sred[t + 64];
        __syncthreads();
        if (t < 32) {
            float v = sred[t] + sred[t + 32];
#pragma unroll
            for (int o = 16; o > 0; o >>= 1) v += __shfl_down_sync(0xffffffffu, v, o);
            if (t == 0) g_partial[blockIdx.x] = v;
        }
    } else {
        if (t == 0) g_partial[blockIdx.x] = 0.f;
    }

    // -------- last-block deterministic final reduction --------
    __shared__ int slast;
    __syncthreads();
    if (t == 0) {
        __threadfence();
        unsigned prev = atomicAdd(&g_done, 1u);
        slast = (prev + 1 == gridDim.x);
    }
    __syncthreads();
    if (slast) {
        float v = 0.f;
        for (int i = t; i < (int)gridDim.x; i += 256) v += g_partial[i];
        sred[t] = v;
        __syncthreads();
        if (t < 128) sred[t] += sred[t + 128];
        __syncthreads();
        if (t < 64) sred[t] += sred[t + 64];
        __syncthreads();
        if (t < 32) {
            float x = sred[t] + sred[t + 32];
#pragma unroll
            for (int o = 16; o > 0; o >>= 1) x += __shfl_down_sync(0xffffffffu, x, o);
            if (t == 0) out[0] = x;
        }
    }
}

// ---------------- launcher ----------------
extern "C" void kernel_launch(void* const* d_in, const int* in_sizes, int n_in,
                              void* d_out, int out_size)
{
    const float* desc    = (const float*)d_in[0];
    const void*  species = d_in[1];
    const float* W0 = (const float*)d_in[2];
    const float* b0 = (const float*)d_in[3];
    const float* W1 = (const float*)d_in[4];
    const float* b1 = (const float*)d_in[5];
    const float* W2 = (const float*)d_in[6];
    const float* b2 = (const float*)d_in[7];

    int n = in_sizes[1];
    if (n > MAXN) n = MAXN;

    int nb_atoms = (n + 255) / 256;
    if (nb_atoms > MAXCB) nb_atoms = MAXCB;
    int nb_mlp = (n + TM - 1) / TM + NOS;
    if (nb_mlp > MAXNB) nb_mlp = MAXNB;

    cudaFuncSetAttribute(k_mlp, cudaFuncAttributeMaxDynamicSharedMemorySize, SMEM_BYTES);

    k_count<<<nb_atoms, 256>>>(species, n);
    k_offsets<<<1, 128>>>(nb_atoms);
    k_scatter<<<nb_atoms, 256>>>(species, n);
    k_mlp<<<nb_mlp, 256, SMEM_BYTES>>>(desc, W0, b0, W1, b1, W2, b2, (float*)d_out);
}